// round 16
// baseline (speedup 1.0000x reference)
#include <cuda_runtime.h>
#include <cuda_fp16.h>
#include <math.h>

#define NN 50000
#define EE 400000
#define IN_CH 16
#define HID 32
#define KDIM 512          // HID*IN_CH
#define SROW 8192         // KDIM*IN_CH
#define CH 2560           // dst-chunk size
#define NCHUNK 20
#define JSLICE 8
#define JLEN 1024         // SROW / JSLICE
#define K1GRID 2048
#define AS_STRIDE 72

// ---------------- scratch (static device globals; no allocations) ----------------
__device__ __half  g_Sh[2][(size_t)CH * SROW];   // double-buffered S, 2 x 42 MB
__device__ float   g_P[2][JSLICE * CH * 32];     // double-buffered partials
__device__ __half  g_pk[(size_t)EE * 32];        // dst-sorted payload: [ea fp16 x16 | x fp16 x16]
__device__ __half  g_w2t[32 * SROW];             // w2 permuted to S-fragment layout
__device__ unsigned g_w1f[8 * 4 * 4 * 32];       // w1 A-fragments: [warp][mtile][q][lane]
__device__ float   g_Xsum[NN * 16];
__device__ float   g_x1[NN * 32];
__device__ float   g_xw[NN * 32];
__device__ float   g_x2[NN * 32];
__device__ float   g_dis[NN];
__device__ int     g_cnt[NN];
__device__ int     g_offs[NN + 1];
__device__ int     g_cursor[NN];
__device__ int     g_elist[EE];
__device__ int     g_src[EE];
__device__ int     g_dst[EE];
__device__ int     g_is64;

// ---------------- [0] detect dtype + zero counters + pack weights ----------------
__global__ void k_dzw(const void* __restrict__ ei, const float* __restrict__ w2,
                      const float* __restrict__ w1) {
    int idx = blockIdx.x * blockDim.x + threadIdx.x;
    if (idx < NN) g_cnt[idx] = 0;
    if (idx == 0) {
        const long long* p = (const long long*)ei;
        int ok = 1;
        #pragma unroll
        for (int q = 0; q < 16; ++q) {
            long long v = p[q];
            if (v < 0 || v >= NN) ok = 0;
        }
        g_is64 = ok;
    }
    // w2t in the S-fragment contraction order:
    // jp = u*2 + h ; u -> w,m,rh,g,t4,n ; K = 64w+16m+8rh+g ; i = 8n+2t4+h
    if (idx < 32 * SROW) {
        int o  = idx >> 13;
        int jp = idx & (SROW - 1);
        int u = jp >> 1, h = jp & 1;
        int w  = u >> 9;
        int m  = (u >> 7) & 3;
        int rh = (u >> 6) & 1;
        int gg = (u >> 3) & 7;
        int t4 = (u >> 1) & 3;
        int n  = u & 1;
        int K  = 64 * w + 16 * m + 8 * rh + gg;
        int i  = 8 * n + 2 * t4 + h;
        g_w2t[idx] = __float2half(w2[(size_t)K * KDIM + i * 32 + o]);
    }
    // w1 A-fragments (m16k16, row = k, col = i)
    if (idx < 4096) {
        int w = idx >> 9, m = (idx >> 7) & 3, q = (idx >> 5) & 3, l = idx & 31;
        int gg = l >> 2, t4 = l & 3;
        int K  = 64 * w + 16 * m + gg + ((q & 1) << 3);
        int i0 = 2 * t4 + ((q >> 1) << 3);
        __half2 hv = __floats2half2_rn(w1[i0 * KDIM + K], w1[(i0 + 1) * KDIM + K]);
        g_w1f[idx] = *(unsigned*)&hv;
    }
}

// ---------------- [1] decode edges + histogram ----------------
__global__ void k_prep(const void* __restrict__ ei) {
    int e = blockIdx.x * blockDim.x + threadIdx.x;
    if (e >= EE) return;
    int s, d;
    if (g_is64) {
        s = (int)((const long long*)ei)[e];
        d = (int)((const long long*)ei)[EE + e];
    } else {
        s = ((const int*)ei)[e];
        d = ((const int*)ei)[EE + e];
    }
    s = s < 0 ? 0 : (s >= NN ? NN - 1 : s);
    d = d < 0 ? 0 : (d >= NN ? NN - 1 : d);
    g_src[e] = s;
    g_dst[e] = d;
    atomicAdd(&g_cnt[d], 1);
}

// ---------------- [2] one-pass block scan (+ degree norms) ----------------
#define SCAN_PER 49
__global__ void k_scan() {
    __shared__ int wsum[32];
    int t = threadIdx.x, lane = t & 31, w = t >> 5;
    int base = t * SCAN_PER;
    int sum = 0;
    #pragma unroll 7
    for (int i = 0; i < SCAN_PER; ++i) {
        int idx = base + i;
        if (idx < NN) sum += g_cnt[idx];
    }
    int inc = sum;
    #pragma unroll
    for (int off = 1; off < 32; off <<= 1) {
        int y = __shfl_up_sync(0xffffffffu, inc, off);
        if (lane >= off) inc += y;
    }
    if (lane == 31) wsum[w] = inc;
    __syncthreads();
    if (w == 0) {
        int s = wsum[lane];
        #pragma unroll
        for (int off = 1; off < 32; off <<= 1) {
            int y = __shfl_up_sync(0xffffffffu, s, off);
            if (lane >= off) s += y;
        }
        wsum[lane] = s;
    }
    __syncthreads();
    int run = inc - sum + (w > 0 ? wsum[w - 1] : 0);
    #pragma unroll 7
    for (int i = 0; i < SCAN_PER; ++i) {
        int idx = base + i;
        if (idx < NN) {
            int v = g_cnt[idx];
            g_offs[idx]   = run;
            g_cursor[idx] = run;
            g_dis[idx]    = rsqrtf((float)(v + 1));
            run += v;
        }
    }
    if (t == 0) g_offs[NN] = EE;
}

// ---------------- [3] scatter edges into dst-CSR ----------------
__global__ void k_scatter() {
    int e = blockIdx.x * blockDim.x + threadIdx.x;
    if (e >= EE) return;
    int pos = atomicAdd(&g_cursor[g_dst[e]], 1);
    if (pos >= 0 && pos < EE) g_elist[pos] = e;
}

// ---------------- [4] build contiguous dst-sorted payload ----------------
__global__ void k_pack(const float* __restrict__ x, const float* __restrict__ ea) {
    int gid = blockIdx.x * blockDim.x + threadIdx.x;
    if (gid >= EE * 32) return;
    int p = gid >> 5;
    int j = gid & 31;
    int e = g_elist[p];
    float v;
    if (j < 16) v = ea[(size_t)e * 16 + j];
    else        v = x[(size_t)g_src[e] * 16 + (j - 16)];
    g_pk[(size_t)p * 32 + j] = __float2half(v);
}

// ================= combo roles =================

// --- role A: K1 via tensor cores. Warp w owns k in [64w, 64w+64). ---
__device__ __forceinline__ void k1_role(
    unsigned char* sm, int bid, int ngrid, int cc, int dn,
    const float* __restrict__ b1)
{
    int t = threadIdx.x;
    int w = t >> 5, lane = t & 31, gg = lane >> 2, t4 = lane & 3;
    __half* Sbuf = g_Sh[cc & 1];
    int d0 = cc * CH;

    unsigned w1f[4][4];
    #pragma unroll
    for (int m = 0; m < 4; ++m)
        #pragma unroll
        for (int q = 0; q < 4; ++q)
            w1f[m][q] = g_w1f[((w * 4 + m) * 4 + q) * 32 + lane];
    unsigned biasL[4], biasH[4];
    #pragma unroll
    for (int m = 0; m < 4; ++m) {
        int K = 64 * w + 16 * m + gg;
        __half2 hl = __float2half2_rn(b1[K]);
        __half2 hh = __float2half2_rn(b1[K + 8]);
        biasL[m] = *(unsigned*)&hl;
        biasH[m] = *(unsigned*)&hh;
    }
    const __half2 hz2 = __float2half2_rn(0.f);

    // payload smem: ea 16 rows x 48B (32B used), x same at +768
    unsigned* ea_u = (unsigned*)sm;
    unsigned* x_u  = (unsigned*)(sm + 768);
    __half*   x_h  = (__half*)(sm + 768);

    int tI = lane >> 3, r = lane & 7;
    unsigned ea_ld = (unsigned)__cvta_generic_to_shared(
        sm + ((tI & 2) ? (8 + r) : r) * 48 + ((tI & 1) ? 16 : 0));
    unsigned x_ld = (unsigned)__cvta_generic_to_shared(
        sm + 768 + ((tI & 1) ? (8 + r) : r) * 48 + ((tI & 2) ? 16 : 0));

    int slot = t >> 4;
    int jj   = t & 15;

    int dl = bid;
    int nbeg = 0, nend = 0;
    if (dl < dn) { nbeg = g_offs[d0 + dl]; nend = g_offs[d0 + dl + 1]; }
    unsigned pf = 0;
    int pfpos = -1;
    if (dl < dn && nend > nbeg) {
        pfpos = nbeg;
        if (slot < nend - nbeg)
            pf = *(const unsigned*)(g_pk + ((size_t)(nbeg + slot) * 32 + jj * 2));
    }

    while (dl < dn) {
        int beg = nbeg, end = nend;
        int dl2 = dl + ngrid;
        if (dl2 < dn) { nbeg = g_offs[d0 + dl2]; nend = g_offs[d0 + dl2 + 1]; }
        else          { nbeg = 0; nend = 0; }

        // f16 accumulators: Sacc[m][n][rh] = half2 (cols 2t4,2t4+1), rh = row half
        unsigned Sacc[4][2][2];
        #pragma unroll
        for (int m = 0; m < 4; ++m)
            #pragma unroll
            for (int n = 0; n < 2; ++n) {
                Sacc[m][n][0] = 0u; Sacc[m][n][1] = 0u;
            }
        float xsum = 0.f;

        for (int base = beg; base < end; base += 16) {
            int nc = end - base; if (nc > 16) nc = 16;
            if (pfpos != base) {
                if (slot < nc)
                    pf = *(const unsigned*)(g_pk + ((size_t)(base + slot) * 32 + jj * 2));
            }
            __syncthreads();
            {
                unsigned v = (slot < nc) ? pf : 0u;
                if (jj < 8) ea_u[slot * 12 + jj] = v;
                else        x_u[slot * 12 + (jj - 8)] = v;
            }
            __syncthreads();
            // prefetch next batch
            {
                int nb = base + 16;
                int pbeg, lim2;
                if (nb < end) { pbeg = nb;   lim2 = end - nb; }
                else          { pbeg = nbeg; lim2 = nend - nbeg; }
                if (lim2 > 0) {
                    pfpos = pbeg;
                    if (slot < lim2)
                        pf = *(const unsigned*)(g_pk + ((size_t)(pbeg + slot) * 32 + jj * 2));
                } else pfpos = -1;
            }

            unsigned bea0, bea1, bea2, bea3, bx0, bx1, bx2, bx3;
            asm volatile("ldmatrix.sync.aligned.m8n8.x4.shared.b16 {%0,%1,%2,%3}, [%4];"
                         : "=r"(bea0), "=r"(bea1), "=r"(bea2), "=r"(bea3) : "r"(ea_ld));
            asm volatile("ldmatrix.sync.aligned.m8n8.x4.trans.shared.b16 {%0,%1,%2,%3}, [%4];"
                         : "=r"(bx0), "=r"(bx1), "=r"(bx2), "=r"(bx3) : "r"(x_ld));

            if (t < 16) {
                for (int c = 0; c < nc; ++c)
                    xsum += __half2float(x_h[c * 24 + t]);
            }

            #pragma unroll
            for (int m = 0; m < 4; ++m) {
                unsigned r0, r1, r2, r3;
                asm volatile(
                    "mma.sync.aligned.m16n8k16.row.col.f16.f16.f16.f16 "
                    "{%0,%1}, {%2,%3,%4,%5}, {%6,%7}, {%8,%9};"
                    : "=r"(r0), "=r"(r1)
                    : "r"(w1f[m][0]), "r"(w1f[m][1]), "r"(w1f[m][2]), "r"(w1f[m][3]),
                      "r"(bea0), "r"(bea1), "r"(biasL[m]), "r"(biasH[m]));
                asm volatile(
                    "mma.sync.aligned.m16n8k16.row.col.f16.f16.f16.f16 "
                    "{%0,%1}, {%2,%3,%4,%5}, {%6,%7}, {%8,%9};"
                    : "=r"(r2), "=r"(r3)
                    : "r"(w1f[m][0]), "r"(w1f[m][1]), "r"(w1f[m][2]), "r"(w1f[m][3]),
                      "r"(bea2), "r"(bea3), "r"(biasL[m]), "r"(biasH[m]));
                // relu
                { __half2* p = (__half2*)&r0; *p = __hmax2(*p, hz2); }
                { __half2* p = (__half2*)&r1; *p = __hmax2(*p, hz2); }
                { __half2* p = (__half2*)&r2; *p = __hmax2(*p, hz2); }
                { __half2* p = (__half2*)&r3; *p = __hmax2(*p, hz2); }
                // GEMM2: S += r @ x  (f16 accumulate)
                asm volatile(
                    "mma.sync.aligned.m16n8k16.row.col.f16.f16.f16.f16 "
                    "{%0,%1}, {%2,%3,%4,%5}, {%6,%7}, {%0,%1};"
                    : "+r"(Sacc[m][0][0]), "+r"(Sacc[m][0][1])
                    : "r"(r0), "r"(r1), "r"(r2), "r"(r3), "r"(bx0), "r"(bx1));
                asm volatile(
                    "mma.sync.aligned.m16n8k16.row.col.f16.f16.f16.f16 "
                    "{%0,%1}, {%2,%3,%4,%5}, {%6,%7}, {%0,%1};"
                    : "+r"(Sacc[m][1][0]), "+r"(Sacc[m][1][1])
                    : "r"(r0), "r"(r1), "r"(r2), "r"(r3), "r"(bx2), "r"(bx3));
            }
        }

        // store S row (fragment-native layout, coalesced 8B stores)
        __half2* Sp2 = (__half2*)(Sbuf + (size_t)dl * SROW);
        #pragma unroll
        for (int m = 0; m < 4; ++m)
            #pragma unroll
            for (int rh = 0; rh < 2; ++rh) {
                int u0 = (((w * 4 + m) * 2 + rh) * 8 + gg) * 8 + t4 * 2;
                uint2 pv;
                pv.x = Sacc[m][0][rh];
                pv.y = Sacc[m][1][rh];
                *(uint2*)&Sp2[u0] = pv;
            }
        if (t < 16) g_Xsum[(d0 + dl) * 16 + t] = xsum;
        dl = dl2;
    }
}

// --- role B: K2 MMA over a j-slice for chunk cc ---
__device__ __forceinline__ void k2_role(unsigned char* sm, int bid, int cc, int dn)
{
    __half* As = (__half*)sm;
    __half* Bs = (__half*)(sm + 128 * AS_STRIDE * 2);
    const __half* Sbuf = g_Sh[cc & 1];
    float* Pbuf = g_P[cc & 1];

    int tid  = threadIdx.x;
    int warp = tid >> 5;
    int lane = tid & 31;
    int g    = lane >> 2;
    int t4   = lane & 3;
    int slice = bid & (JSLICE - 1);
    int r0    = (bid >> 3) * 128;
    int jbase = slice * JLEN;

    float c0[4], c1[4], c2[4], c3[4];
    #pragma unroll
    for (int nt = 0; nt < 4; ++nt) { c0[nt] = 0.f; c1[nt] = 0.f; c2[nt] = 0.f; c3[nt] = 0.f; }

    for (int it = 0; it < JLEN / 64; ++it) {
        int j0 = jbase + it * 64;
        __syncthreads();
        #pragma unroll
        for (int u = 0; u < 4; ++u) {
            int idx = tid + u * 256;
            int row = idx >> 3;
            int q   = idx & 7;
            int rl  = r0 + row; if (rl >= dn) rl = dn - 1;
            *(uint4*)&As[row * AS_STRIDE + q * 8] =
                ((const uint4*)(Sbuf + (size_t)rl * SROW + j0))[q];
        }
        {
            int row = tid >> 3;
            int q   = tid & 7;
            *(uint4*)&Bs[row * AS_STRIDE + q * 8] =
                ((const uint4*)(g_w2t + (size_t)row * SROW + j0))[q];
        }
        __syncthreads();

        #pragma unroll
        for (int kk = 0; kk < 64; kk += 16) {
            unsigned a0 = *(const unsigned*)&As[(warp * 16 + g    ) * AS_STRIDE + kk     + 2 * t4];
            unsigned a1 = *(const unsigned*)&As[(warp * 16 + g + 8) * AS_STRIDE + kk     + 2 * t4];
            unsigned a2 = *(const unsigned*)&As[(warp * 16 + g    ) * AS_STRIDE + kk + 8 + 2 * t4];
            unsigned a3 = *(const unsigned*)&As[(warp * 16 + g + 8) * AS_STRIDE + kk + 8 + 2 * t4];
            #pragma unroll
            for (int nt = 0; nt < 4; ++nt) {
                unsigned b0 = *(const unsigned*)&Bs[(nt * 8 + g) * AS_STRIDE + kk     + 2 * t4];
                unsigned b1 = *(const unsigned*)&Bs[(nt * 8 + g) * AS_STRIDE + kk + 8 + 2 * t4];
                asm volatile(
                    "mma.sync.aligned.m16n8k16.row.col.f32.f16.f16.f32 "
                    "{%0,%1,%2,%3}, {%4,%5,%6,%7}, {%8,%9}, {%0,%1,%2,%3};"
                    : "+f"(c0[nt]), "+f"(c1[nt]), "+f"(c2[nt]), "+f"(c3[nt])
                    : "r"(a0), "r"(a1), "r"(a2), "r"(a3), "r"(b0), "r"(b1));
            }
        }
    }

    #pragma unroll
    for (int nt = 0; nt < 4; ++nt) {
        int row = r0 + warp * 16 + g;
        int col = nt * 8 + 2 * t4;
        if (row < dn)
            *(float2*)&Pbuf[((size_t)slice * CH + row) * 32 + col] = make_float2(c0[nt], c1[nt]);
        if (row + 8 < dn)
            *(float2*)&Pbuf[((size_t)slice * CH + row + 8) * 32 + col] = make_float2(c2[nt], c3[nt]);
    }
}

// --- role C: reduce partials + NNConv epilogue for chunk cc ---
__device__ __forceinline__ void red_role(
    int bid, int cc, int dn,
    const float* __restrict__ b2, const float* __restrict__ x,
    const float* __restrict__ root, const float* __restrict__ nn_bias)
{
    int gid = bid * 256 + threadIdx.x;
    if (gid >= dn * 32) return;
    const float* Pbuf = g_P[cc & 1];
    int rl = gid >> 5, o = gid & 31;
    int d = cc * CH + rl;
    float v = nn_bias[o];
    #pragma unroll
    for (int s = 0; s < JSLICE; ++s)
        v += Pbuf[((size_t)s * CH + rl) * 32 + o];
    #pragma unroll
    for (int i = 0; i < 16; ++i)
        v = fmaf(g_Xsum[d * 16 + i], b2[i * 32 + o], v);
    #pragma unroll
    for (int c = 0; c < 16; ++c)
        v = fmaf(x[(size_t)d * 16 + c], root[c * 32 + o], v);
    g_x1[d * 32 + o] = fmaxf(v, 0.f);
}

// --- combo: block ranges -> roles ---
__global__ void __launch_bounds__(256, 3) k_combo(
    const float* __restrict__ x, const float* __restrict__ b1,
    const float* __restrict__ b2, const float* __restrict__ root,
    const float* __restrict__ nn_bias,
    int c, int nK2, int nK1, int dnK1, int dnK2, int dnRd)
{
    __shared__ __align__(16) unsigned char sm[(128 + 32) * AS_STRIDE * 2];
    int b = blockIdx.x;
    if (b < nK2) {
        k2_role(sm, b, c - 1, dnK2);
    } else if (b < nK2 + nK1) {
        k1_role(sm, b - nK2, nK1, c, dnK1, b1);
    } else {
        red_role(b - nK2 - nK1, c - 2, dnRd, b2, x, root, nn_bias);
    }
}

// ---------------- K3: xw = x1 @ gcn_w ----------------
__global__ void k3_xw(const float* __restrict__ gcn_w) {
    int gid = blockIdx.x * blockDim.x + threadIdx.x;
    if (gid >= NN * 32) return;
    int d = gid >> 5, o = gid & 31;
    float acc = 0.f;
    #pragma unroll
    for (int c = 0; c < 32; ++c)
        acc = fmaf(g_x1[d * 32 + c], gcn_w[c * 32 + o], acc);
    g_xw[gid] = acc;
}

// ---------------- K4: GCN aggregate via CSR (warp per dst) ----------------
__global__ void k4_gcn(const float* __restrict__ gcn_b) {
    int wid = (blockIdx.x * blockDim.x + threadIdx.x) >> 5;
    int lane = threadIdx.x & 31;
    int nwarps = (gridDim.x * blockDim.x) >> 5;
    for (int d = wid; d < NN; d += nwarps) {
        float dd = g_dis[d];
        float acc = 0.f;
        int beg = g_offs[d], end = g_offs[d + 1];
        for (int j = beg; j < end; ++j) {
            int e = g_elist[j];
            int s = g_src[e];
            acc = fmaf(g_dis[s], g_xw[s * 32 + lane], acc);
        }
        g_x2[d * 32 + lane] = gcn_b[lane] + dd * (dd * g_xw[d * 32 + lane] + acc);
    }
}

// ---------------- K5: edge scorer ----------------
__global__ void k5_score(const float* __restrict__ lin_w, const float* __restrict__ lin_b,
                         float* __restrict__ out) {
    int e = blockIdx.x * blockDim.x + threadIdx.x;
    if (e >= EE) return;
    int s = g_src[e], d = g_dst[e];
    const float4* a = (const float4*)(g_x2 + (size_t)s * 32);
    const float4* b = (const float4*)(g_x2 + (size_t)d * 32);
    const float4* w = (const float4*)lin_w;
    float acc = lin_b[0];
    #pragma unroll
    for (int q = 0; q < 8; ++q) {
        float4 av = a[q], wv = w[q];
        acc += av.x * wv.x + av.y * wv.y + av.z * wv.z + av.w * wv.w;
    }
    #pragma unroll
    for (int q = 0; q < 8; ++q) {
        float4 bv = b[q], wv = w[8 + q];
        acc += bv.x * wv.x + bv.y * wv.y + bv.z * wv.z + bv.w * wv.w;
    }
    out[e] = 1.f / (1.f + expf(-acc));
}

// ---------------- launch ----------------
static inline int dn_of(int c) {
    if (c < 0 || c >= NCHUNK) return 0;
    int d0 = c * CH;
    int dn = NN - d0;
    if (dn > CH) dn = CH;
    return dn > 0 ? dn : 0;
}

extern "C" void kernel_launch(void* const* d_in, const int* in_sizes, int n_in,
                              void* d_out, int out_size) {
    const float* x       = (const float*)d_in[0];
    const void*  ei      = d_in[1];
    const float* ea      = (const float*)d_in[2];
    const float* w1      = (const float*)d_in[3];
    const float* b1      = (const float*)d_in[4];
    const float* w2      = (const float*)d_in[5];
    const float* b2      = (const float*)d_in[6];
    const float* root    = (const float*)d_in[7];
    const float* nn_bias = (const float*)d_in[8];
    const float* gcn_w   = (const float*)d_in[9];
    const float* gcn_b   = (const float*)d_in[10];
    const float* lin_w   = (const float*)d_in[11];
    const float* lin_b   = (const float*)d_in[12];
    float*       out     = (float*)d_out;

    k_dzw<<<(32 * SROW + 255) / 256, 256>>>(ei, w2, w1);
    k_prep<<<(EE + 255) / 256, 256>>>(ei);
    k_scan<<<1, 1024>>>();
    k_scatter<<<(EE + 255) / 256, 256>>>();
    k_pack<<<(EE * 32 + 255) / 256, 256>>>(x, ea);

    // software pipeline: combo(c) = k2(c-1) || k1(c) || reduce(c-2)
    for (int c = 0; c <= NCHUNK + 1; ++c) {
        int dnK1 = dn_of(c);
        int dnK2 = dn_of(c - 1);
        int dnRd = dn_of(c - 2);
        int nK2 = dnK2 ? ((dnK2 + 127) / 128) * JSLICE : 0;
        int nK1 = dnK1 ? (dnK1 < K1GRID ? dnK1 : K1GRID) : 0;
        int nRd = dnRd ? (dnRd * 32 + 255) / 256 : 0;
        int grid = nK2 + nK1 + nRd;
        if (grid > 0)
            k_combo<<<grid, 256>>>(x, b1, b2, root, nn_bias, c, nK2, nK1, dnK1, dnK2, dnRd);
    }

    k3_xw<<<(NN * 32 + 255) / 256, 256>>>(gcn_w);
    k4_gcn<<<512, 256>>>(gcn_b);
    k5_score<<<(EE + 255) / 256, 256>>>(lin_w, lin_b, out);
}